// round 1
// baseline (speedup 1.0000x reference)
#include <cuda_runtime.h>

#define NUc 100000
#define NIc 50000
#define NVc 150000   // NUc + NIc
#define Dc  64
#define NEc 1000000

// ---------------- scratch (static device allocations are allowed) -----------
__device__ float g_all[(size_t)NVc * Dc];  // current embeddings (concat u,i)
__device__ float g_acc[(size_t)NVc * Dc];  // running sum for final mean
__device__ float g_X1 [(size_t)NVc * Dc];  // X * D^-1/2
__device__ float g_E  [(size_t)NVc * Dc];  // edge-aggregated (hyperedge) embs
__device__ float g_Y  [(size_t)NVc * Dc];  // second aggregation
__device__ int   g_deg[NVc];
__device__ float g_isq[NVc];               // deg^-1/2 (0 if deg==0)
__device__ float g_inv[NVc];               // deg^-1   (0 if deg==0)

// vector reduction to global (sm_90+): 1 request carries 16B
__device__ __forceinline__ void red4(float4* p, float4 v) {
    asm volatile("red.global.add.v4.f32 [%0], {%1,%2,%3,%4};"
                 :: "l"(p), "f"(v.x), "f"(v.y), "f"(v.z), "f"(v.w)
                 : "memory");
}

// ---------------- kernels ---------------------------------------------------

__global__ void k_zero_deg() {
    int i = blockIdx.x * blockDim.x + threadIdx.x;
    if (i < NVc) g_deg[i] = 0;
}

__global__ void k_count(const int* __restrict__ eu, const int* __restrict__ ei) {
    int e = blockIdx.x * blockDim.x + threadIdx.x;
    if (e < NEc) {
        atomicAdd(&g_deg[eu[e]], 1);
        atomicAdd(&g_deg[NUc + ei[e]], 1);
    }
}

__global__ void k_norm() {
    int n = blockIdx.x * blockDim.x + threadIdx.x;
    if (n < NVc) {
        int d = g_deg[n];
        if (d > 0) {
            float fd = (float)d;
            g_isq[n] = rsqrtf(fd);
            g_inv[n] = 1.0f / fd;
        } else {
            g_isq[n] = 0.0f;
            g_inv[n] = 0.0f;
        }
    }
}

__global__ void k_init(const float4* __restrict__ u4, const float4* __restrict__ i4) {
    int idx = blockIdx.x * blockDim.x + threadIdx.x;  // over NVc*16 float4
    if (idx < NVc * (Dc / 4)) {
        float4 v = (idx < NUc * (Dc / 4)) ? u4[idx] : i4[idx - NUc * (Dc / 4)];
        ((float4*)g_all)[idx] = v;
        ((float4*)g_acc)[idx] = v;
    }
}

// X1 = all * isq ; zero E and Y
__global__ void k_prep() {
    int idx = blockIdx.x * blockDim.x + threadIdx.x;
    if (idx < NVc * (Dc / 4)) {
        int n = idx >> 4;
        float s = g_isq[n];
        float4 v = ((const float4*)g_all)[idx];
        v.x *= s; v.y *= s; v.z *= s; v.w *= s;
        ((float4*)g_X1)[idx] = v;
        float4 z = make_float4(0.f, 0.f, 0.f, 0.f);
        ((float4*)g_E)[idx] = z;
        ((float4*)g_Y)[idx] = z;
    }
}

// pass 1: E[i] += X1[u];  E[u] += X1[i]    (fused both directions)
__global__ void k_scat1(const int* __restrict__ eu, const int* __restrict__ ei) {
    int t = blockIdx.x * blockDim.x + threadIdx.x;  // NEc*16 threads
    if (t < NEc * 16) {
        int e = t >> 4, c = t & 15;
        int u = eu[e];
        int it = NUc + ei[e];
        const float4* X14 = (const float4*)g_X1;
        float4 a = X14[u * 16 + c];
        float4 b = X14[it * 16 + c];
        red4(&((float4*)g_E)[it * 16 + c], a);
        red4(&((float4*)g_E)[u * 16 + c], b);
    }
}

// pass 2: Y[u] += E[i]*inv_i ;  Y[i] += E[u]*inv_u
__global__ void k_scat2(const int* __restrict__ eu, const int* __restrict__ ei) {
    int t = blockIdx.x * blockDim.x + threadIdx.x;
    if (t < NEc * 16) {
        int e = t >> 4, c = t & 15;
        int u = eu[e];
        int it = NUc + ei[e];
        float si = g_inv[it];
        float su = g_inv[u];
        const float4* E4 = (const float4*)g_E;
        float4 a = E4[it * 16 + c];
        a.x *= si; a.y *= si; a.z *= si; a.w *= si;
        float4 b = E4[u * 16 + c];
        b.x *= su; b.y *= su; b.z *= su; b.w *= su;
        red4(&((float4*)g_Y)[u * 16 + c], a);
        red4(&((float4*)g_Y)[it * 16 + c], b);
    }
}

// per-node: g = Y*isq; h1 = lrelu(g@Wgc^T + bgc + x); h2 = lrelu((x*g)@Wbi^T + bbi)
// new = L2norm(h1+h2); all = new; acc += new.   One warp per node.
__global__ void __launch_bounds__(256) k_layer(const float* __restrict__ Wgc,
                                               const float* __restrict__ bgc,
                                               const float* __restrict__ Wbi,
                                               const float* __restrict__ bbi) {
    __shared__ float sWg[64 * 64];  // transposed: sWg[k*64+j] = Wgc[j*64+k]
    __shared__ float sWb[64 * 64];
    __shared__ float sbg[64], sbb[64];

    for (int idx = threadIdx.x; idx < 4096; idx += 256) {
        int k = idx >> 6, j = idx & 63;
        sWg[idx] = Wgc[j * 64 + k];
        sWb[idx] = Wbi[j * 64 + k];
    }
    if (threadIdx.x < 64) {
        sbg[threadIdx.x] = bgc[threadIdx.x];
        sbb[threadIdx.x] = bbi[threadIdx.x];
    }
    __syncthreads();

    int lane = threadIdx.x & 31;
    int w    = threadIdx.x >> 5;

    for (int n = blockIdx.x * 8 + w; n < NVc; n += gridDim.x * 8) {
        float isq = g_isq[n];
        float g0 = g_Y[n * 64 + lane]      * isq;
        float g1 = g_Y[n * 64 + 32 + lane] * isq;
        float x0 = g_all[n * 64 + lane];
        float x1 = g_all[n * 64 + 32 + lane];
        float m0 = x0 * g0, m1 = x1 * g1;

        float a0 = 0.f, a1 = 0.f, b0 = 0.f, b1 = 0.f;
        #pragma unroll
        for (int k = 0; k < 32; k++) {
            float gk = __shfl_sync(0xffffffffu, g0, k);
            float mk = __shfl_sync(0xffffffffu, m0, k);
            a0 = fmaf(sWg[k * 64 + lane],      gk, a0);
            a1 = fmaf(sWg[k * 64 + 32 + lane], gk, a1);
            b0 = fmaf(sWb[k * 64 + lane],      mk, b0);
            b1 = fmaf(sWb[k * 64 + 32 + lane], mk, b1);
        }
        #pragma unroll
        for (int k = 0; k < 32; k++) {
            float gk = __shfl_sync(0xffffffffu, g1, k);
            float mk = __shfl_sync(0xffffffffu, m1, k);
            a0 = fmaf(sWg[(k + 32) * 64 + lane],      gk, a0);
            a1 = fmaf(sWg[(k + 32) * 64 + 32 + lane], gk, a1);
            b0 = fmaf(sWb[(k + 32) * 64 + lane],      mk, b0);
            b1 = fmaf(sWb[(k + 32) * 64 + 32 + lane], mk, b1);
        }

        float h0 = a0 + sbg[lane]      + x0; h0 = h0 > 0.f ? h0 : 0.2f * h0;
        float h1 = a1 + sbg[lane + 32] + x1; h1 = h1 > 0.f ? h1 : 0.2f * h1;
        float p0 = b0 + sbb[lane];           p0 = p0 > 0.f ? p0 : 0.2f * p0;
        float p1 = b1 + sbb[lane + 32];      p1 = p1 > 0.f ? p1 : 0.2f * p1;

        float n0 = h0 + p0, n1 = h1 + p1;
        float s = n0 * n0 + n1 * n1;
        #pragma unroll
        for (int o = 16; o; o >>= 1) s += __shfl_xor_sync(0xffffffffu, s, o);
        float invn = 1.0f / fmaxf(sqrtf(s), 1e-12f);
        n0 *= invn; n1 *= invn;

        g_all[n * 64 + lane]       = n0;
        g_all[n * 64 + 32 + lane]  = n1;
        g_acc[n * 64 + lane]      += n0;
        g_acc[n * 64 + 32 + lane] += n1;
    }
}

__global__ void k_final(float4* __restrict__ out) {
    int idx = blockIdx.x * blockDim.x + threadIdx.x;
    if (idx < NVc * (Dc / 4)) {
        float4 v = ((const float4*)g_acc)[idx];
        v.x *= 0.25f; v.y *= 0.25f; v.z *= 0.25f; v.w *= 0.25f;
        out[idx] = v;
    }
}

// ---------------- launch ----------------------------------------------------

extern "C" void kernel_launch(void* const* d_in, const int* in_sizes, int n_in,
                              void* d_out, int out_size) {
    const float* u_emb = (const float*)d_in[0];
    const float* i_emb = (const float*)d_in[1];
    const float* Wgc   = (const float*)d_in[2];
    const float* bgc   = (const float*)d_in[3];
    const float* Wbi   = (const float*)d_in[4];
    const float* bbi   = (const float*)d_in[5];
    const int*   eu    = (const int*)d_in[6];
    const int*   ei    = (const int*)d_in[7];
    float* out = (float*)d_out;

    const int nodeVecBlocks = (NVc * (Dc / 4) + 255) / 256;   // 9375
    const int edgeBlocks    = (NEc * 16 + 255) / 256;          // 62500

    k_zero_deg<<<(NVc + 255) / 256, 256>>>();
    k_count<<<(NEc + 255) / 256, 256>>>(eu, ei);
    k_norm<<<(NVc + 255) / 256, 256>>>();
    k_init<<<nodeVecBlocks, 256>>>((const float4*)u_emb, (const float4*)i_emb);

    for (int l = 0; l < 3; l++) {
        k_prep<<<nodeVecBlocks, 256>>>();
        k_scat1<<<edgeBlocks, 256>>>(eu, ei);
        k_scat2<<<edgeBlocks, 256>>>(eu, ei);
        k_layer<<<(NVc + 7) / 8, 256>>>(Wgc + l * 4096, bgc + l * 64,
                                        Wbi + l * 4096, bbi + l * 64);
    }

    k_final<<<nodeVecBlocks, 256>>>((float4*)out);
}

// round 2
// speedup vs baseline: 2.5863x; 2.5863x over previous
#include <cuda_runtime.h>

#define NUc 100000
#define NIc 50000
#define NVc 150000   // NUc + NIc
#define Dc  64
#define NEc 1000000

// ---------------- scratch -----------------------------------------------
__device__ float g_all[(size_t)NVc * Dc];  // current embeddings (concat u,i)
__device__ float g_acc[(size_t)NVc * Dc];  // running sum for final mean
__device__ float g_X1 [(size_t)NVc * Dc];  // X * D^-1/2 (input to gather)
__device__ float g_E  [(size_t)NVc * Dc];  // hyperedge embs, pre-scaled by De^-1
__device__ int   g_deg[NVc];
__device__ float g_isq[NVc];               // deg^-1/2 (0 if deg==0)
__device__ float g_inv[NVc];               // deg^-1   (0 if deg==0)
__device__ int   g_off[NVc];               // CSR row offsets (exclusive scan of deg)
__device__ int   g_cur[NVc];               // fill cursors
__device__ int   g_adj[NEc * 2];           // neighbor lists (opposite node id)
__device__ int   g_bsum[256];              // scan partials

// ---------------- degree / normalization --------------------------------

__global__ void k_zero_deg() {
    int i = blockIdx.x * blockDim.x + threadIdx.x;
    if (i < NVc) g_deg[i] = 0;
}

__global__ void k_count(const int* __restrict__ eu, const int* __restrict__ ei) {
    int e = blockIdx.x * blockDim.x + threadIdx.x;
    if (e < NEc) {
        atomicAdd(&g_deg[eu[e]], 1);
        atomicAdd(&g_deg[NUc + ei[e]], 1);
    }
}

__global__ void k_norm() {
    int n = blockIdx.x * blockDim.x + threadIdx.x;
    if (n < NVc) {
        int d = g_deg[n];
        if (d > 0) {
            float fd = (float)d;
            g_isq[n] = rsqrtf(fd);
            g_inv[n] = 1.0f / fd;
        } else {
            g_isq[n] = 0.0f;
            g_inv[n] = 0.0f;
        }
    }
}

// ---------------- exclusive scan of g_deg -> g_off -----------------------

__global__ void k_scan1() {   // 147 blocks x 1024
    __shared__ int s[1024];
    int i = blockIdx.x * 1024 + threadIdx.x;
    int v = (i < NVc) ? g_deg[i] : 0;
    s[threadIdx.x] = v;
    __syncthreads();
    #pragma unroll
    for (int d = 1; d < 1024; d <<= 1) {
        int t = (threadIdx.x >= d) ? s[threadIdx.x - d] : 0;
        __syncthreads();
        s[threadIdx.x] += t;
        __syncthreads();
    }
    if (i < NVc) g_off[i] = s[threadIdx.x] - v;   // exclusive
    if (threadIdx.x == 1023) g_bsum[blockIdx.x] = s[1023];
}

__global__ void k_scan2(int nblocks) {  // 1 block x 256
    __shared__ int s[256];
    int v = (threadIdx.x < nblocks) ? g_bsum[threadIdx.x] : 0;
    s[threadIdx.x] = v;
    __syncthreads();
    #pragma unroll
    for (int d = 1; d < 256; d <<= 1) {
        int t = (threadIdx.x >= d) ? s[threadIdx.x - d] : 0;
        __syncthreads();
        s[threadIdx.x] += t;
        __syncthreads();
    }
    g_bsum[threadIdx.x] = s[threadIdx.x] - v;     // exclusive
}

__global__ void k_scan3() {
    int i = blockIdx.x * blockDim.x + threadIdx.x;
    if (i < NVc) {
        int o = g_off[i] + g_bsum[i >> 10];
        g_off[i] = o;
        g_cur[i] = o;
    }
}

__global__ void k_fill(const int* __restrict__ eu, const int* __restrict__ ei) {
    int e = blockIdx.x * blockDim.x + threadIdx.x;
    if (e < NEc) {
        int u = eu[e];
        int it = NUc + ei[e];
        int pu = atomicAdd(&g_cur[u], 1);
        g_adj[pu] = it;
        int pi = atomicAdd(&g_cur[it], 1);
        g_adj[pi] = u;
    }
}

// ---------------- embedding init ------------------------------------------

__global__ void k_init(const float4* __restrict__ u4, const float4* __restrict__ i4) {
    int idx = blockIdx.x * blockDim.x + threadIdx.x;
    if (idx < NVc * (Dc / 4)) {
        float4 v = (idx < NUc * (Dc / 4)) ? u4[idx] : i4[idx - NUc * (Dc / 4)];
        ((float4*)g_all)[idx] = v;
        ((float4*)g_acc)[idx] = v;
        int n = idx >> 4;
        float s = g_isq[n];
        float4 w = make_float4(v.x * s, v.y * s, v.z * s, v.w * s);
        ((float4*)g_X1)[idx] = w;
    }
}

// ---------------- gather 1: E'[n] = inv[n] * sum_{opp in N(n)} X1[opp] ----
// one warp per node; lane handles columns (lane, lane+32)

__global__ void __launch_bounds__(256) k_gatherE() {
    int lane = threadIdx.x & 31;
    int w    = threadIdx.x >> 5;
    int n = blockIdx.x * 8 + w;
    if (n >= NVc) return;

    int base = g_off[n];
    int deg  = g_deg[n];
    const int* __restrict__ adj = g_adj + base;
    const float* __restrict__ X = g_X1;

    float s0 = 0.f, s1 = 0.f;
    int j = 0;
    for (; j + 4 <= deg; j += 4) {
        int o0 = adj[j], o1 = adj[j+1], o2 = adj[j+2], o3 = adj[j+3];
        float a0 = X[o0*64 + lane],     a1 = X[o1*64 + lane];
        float a2 = X[o2*64 + lane],     a3 = X[o3*64 + lane];
        float b0 = X[o0*64 + 32 + lane], b1 = X[o1*64 + 32 + lane];
        float b2 = X[o2*64 + 32 + lane], b3 = X[o3*64 + 32 + lane];
        s0 += (a0 + a1) + (a2 + a3);
        s1 += (b0 + b1) + (b2 + b3);
    }
    for (; j < deg; j++) {
        int o = adj[j];
        s0 += X[o*64 + lane];
        s1 += X[o*64 + 32 + lane];
    }
    float inv = g_inv[n];
    g_E[n*64 + lane]      = s0 * inv;
    g_E[n*64 + 32 + lane] = s1 * inv;
}

// ---------------- fused: gather2 + g-scale + 2x GEMV + lrelu + L2norm ----
// Y[n] = sum E'[opp]; g = Y*isq; h1 = lrelu(g@Wgc^T+bgc+x); h2 = lrelu((x*g)@Wbi^T+bbi)
// new = L2norm(h1+h2); all=new; acc+=new; X1=new*isq (for next layer)

__global__ void __launch_bounds__(256) k_layer(const float* __restrict__ Wgc,
                                               const float* __restrict__ bgc,
                                               const float* __restrict__ Wbi,
                                               const float* __restrict__ bbi) {
    __shared__ float sWg[64 * 64];  // transposed: sWg[k*64+j] = Wgc[j*64+k]
    __shared__ float sWb[64 * 64];
    __shared__ float sbg[64], sbb[64];

    for (int idx = threadIdx.x; idx < 4096; idx += 256) {
        int k = idx >> 6, jj = idx & 63;
        sWg[idx] = Wgc[jj * 64 + k];
        sWb[idx] = Wbi[jj * 64 + k];
    }
    if (threadIdx.x < 64) {
        sbg[threadIdx.x] = bgc[threadIdx.x];
        sbb[threadIdx.x] = bbi[threadIdx.x];
    }
    __syncthreads();

    int lane = threadIdx.x & 31;
    int w    = threadIdx.x >> 5;

    for (int n = blockIdx.x * 8 + w; n < NVc; n += gridDim.x * 8) {
        // --- gather Y from pre-scaled E ---
        int base = g_off[n];
        int deg  = g_deg[n];
        const int* __restrict__ adj = g_adj + base;
        float y0 = 0.f, y1 = 0.f;
        int j = 0;
        for (; j + 4 <= deg; j += 4) {
            int o0 = adj[j], o1 = adj[j+1], o2 = adj[j+2], o3 = adj[j+3];
            float a0 = g_E[o0*64 + lane],     a1 = g_E[o1*64 + lane];
            float a2 = g_E[o2*64 + lane],     a3 = g_E[o3*64 + lane];
            float b0 = g_E[o0*64 + 32 + lane], b1 = g_E[o1*64 + 32 + lane];
            float b2 = g_E[o2*64 + 32 + lane], b3 = g_E[o3*64 + 32 + lane];
            y0 += (a0 + a1) + (a2 + a3);
            y1 += (b0 + b1) + (b2 + b3);
        }
        for (; j < deg; j++) {
            int o = adj[j];
            y0 += g_E[o*64 + lane];
            y1 += g_E[o*64 + 32 + lane];
        }

        float isq = g_isq[n];
        float g0 = y0 * isq;
        float g1 = y1 * isq;
        float x0 = g_all[n * 64 + lane];
        float x1 = g_all[n * 64 + 32 + lane];
        float m0 = x0 * g0, m1 = x1 * g1;

        float a0 = 0.f, a1 = 0.f, b0 = 0.f, b1 = 0.f;
        #pragma unroll
        for (int k = 0; k < 32; k++) {
            float gk = __shfl_sync(0xffffffffu, g0, k);
            float mk = __shfl_sync(0xffffffffu, m0, k);
            a0 = fmaf(sWg[k * 64 + lane],      gk, a0);
            a1 = fmaf(sWg[k * 64 + 32 + lane], gk, a1);
            b0 = fmaf(sWb[k * 64 + lane],      mk, b0);
            b1 = fmaf(sWb[k * 64 + 32 + lane], mk, b1);
        }
        #pragma unroll
        for (int k = 0; k < 32; k++) {
            float gk = __shfl_sync(0xffffffffu, g1, k);
            float mk = __shfl_sync(0xffffffffu, m1, k);
            a0 = fmaf(sWg[(k + 32) * 64 + lane],      gk, a0);
            a1 = fmaf(sWg[(k + 32) * 64 + 32 + lane], gk, a1);
            b0 = fmaf(sWb[(k + 32) * 64 + lane],      mk, b0);
            b1 = fmaf(sWb[(k + 32) * 64 + 32 + lane], mk, b1);
        }

        float h0 = a0 + sbg[lane]      + x0; h0 = h0 > 0.f ? h0 : 0.2f * h0;
        float h1 = a1 + sbg[lane + 32] + x1; h1 = h1 > 0.f ? h1 : 0.2f * h1;
        float p0 = b0 + sbb[lane];           p0 = p0 > 0.f ? p0 : 0.2f * p0;
        float p1 = b1 + sbb[lane + 32];      p1 = p1 > 0.f ? p1 : 0.2f * p1;

        float n0 = h0 + p0, n1 = h1 + p1;
        float s = n0 * n0 + n1 * n1;
        #pragma unroll
        for (int o = 16; o; o >>= 1) s += __shfl_xor_sync(0xffffffffu, s, o);
        float invn = 1.0f / fmaxf(sqrtf(s), 1e-12f);
        n0 *= invn; n1 *= invn;

        g_all[n * 64 + lane]       = n0;
        g_all[n * 64 + 32 + lane]  = n1;
        g_acc[n * 64 + lane]      += n0;
        g_acc[n * 64 + 32 + lane] += n1;
        g_X1[n * 64 + lane]        = n0 * isq;
        g_X1[n * 64 + 32 + lane]   = n1 * isq;
    }
}

__global__ void k_final(float4* __restrict__ out) {
    int idx = blockIdx.x * blockDim.x + threadIdx.x;
    if (idx < NVc * (Dc / 4)) {
        float4 v = ((const float4*)g_acc)[idx];
        v.x *= 0.25f; v.y *= 0.25f; v.z *= 0.25f; v.w *= 0.25f;
        out[idx] = v;
    }
}

// ---------------- launch ----------------------------------------------------

extern "C" void kernel_launch(void* const* d_in, const int* in_sizes, int n_in,
                              void* d_out, int out_size) {
    const float* u_emb = (const float*)d_in[0];
    const float* i_emb = (const float*)d_in[1];
    const float* Wgc   = (const float*)d_in[2];
    const float* bgc   = (const float*)d_in[3];
    const float* Wbi   = (const float*)d_in[4];
    const float* bbi   = (const float*)d_in[5];
    const int*   eu    = (const int*)d_in[6];
    const int*   ei    = (const int*)d_in[7];
    float* out = (float*)d_out;

    const int nodeVecBlocks = (NVc * (Dc / 4) + 255) / 256;  // 9375
    const int nodeBlocks    = (NVc + 255) / 256;             // 586
    const int edgeBlocks    = (NEc + 255) / 256;             // 3907
    const int scanBlocks    = (NVc + 1023) / 1024;           // 147
    const int warpNodeBlocks = (NVc + 7) / 8;                // 18750

    k_zero_deg<<<nodeBlocks, 256>>>();
    k_count<<<edgeBlocks, 256>>>(eu, ei);
    k_norm<<<nodeBlocks, 256>>>();
    k_scan1<<<scanBlocks, 1024>>>();
    k_scan2<<<1, 256>>>(scanBlocks);
    k_scan3<<<nodeBlocks, 256>>>();
    k_fill<<<edgeBlocks, 256>>>(eu, ei);
    k_init<<<nodeVecBlocks, 256>>>((const float4*)u_emb, (const float4*)i_emb);

    for (int l = 0; l < 3; l++) {
        k_gatherE<<<warpNodeBlocks, 256>>>();
        k_layer<<<888, 256>>>(Wgc + l * 4096, bgc + l * 64,
                              Wbi + l * 4096, bbi + l * 64);
    }

    k_final<<<nodeVecBlocks, 256>>>((float4*)out);
}